// round 12
// baseline (speedup 1.0000x reference)
#include <cuda_runtime.h>
#include <math.h>

#define EPS_F 1.1920928955078125e-07f
#define RED_THREADS 256
#define MAX_C 64
#define CHUNK_L4 32     // 32 float4 x 64 rows x 16B = 32KB per unit
#define RED_GRID 888    // ~6 blocks/SM persistent-style

// scratch (allocation-free rule): partial sums + final stats
__device__ float g_partials[256 * MAX_C * 2];  // [b][chunk][{sum,sumsq}]; inactive slots stay 0
__device__ float g_stats[512];                 // [b][{scale,bias}]

// ---------------------------------------------------------------------------
// Kernel 1: balanced reduce. Each block builds the active-chunk prefix table
// from zero_pos (cheap, in-block), then grid-strides over exactly the N active
// uniform 32KB units. No inactive blocks, no wave raggedness.
// Unit u -> (b, k): binary search prefix table. Warp = 32 consecutive l4 at
// one c (512B coalesced); 8 c-iterations per thread -> MLP 8.
// ---------------------------------------------------------------------------
__global__ void reduce_kernel(const float* __restrict__ data,
                              const int* __restrict__ zero_pos,
                              int C, int L) {
    __shared__ int sh_off[65];
    int tid = threadIdx.x;

    if (tid == 0) {
        int acc = 0;
        for (int b = 0; b < 64; b++) {
            sh_off[b] = acc;
            int zp  = zero_pos[b];
            int zp4 = zp >> 2;
            int zr  = zp & 3;
            int cov = zp4 + (zr ? 1 : 0);            // float4 slots to cover
            acc += (cov + CHUNK_L4 - 1) / CHUNK_L4;  // chunks for this batch
        }
        sh_off[64] = acc;
    }
    __syncthreads();
    int N = sh_off[64];

    size_t L4 = (size_t)(L >> 2);

    __shared__ float sh_s[RED_THREADS];
    __shared__ float sh_q[RED_THREADS];

    for (int u = blockIdx.x; u < N; u += RED_GRID) {
        // binary search: largest b with sh_off[b] <= u
        int lo = 0, hi = 64;
        while (hi - lo > 1) {
            int mid = (lo + hi) >> 1;
            if (sh_off[mid] <= u) lo = mid; else hi = mid;
        }
        int b = lo;
        int k = u - sh_off[b];

        int zp   = zero_pos[b];
        int zp4  = zp >> 2;
        int zrem = zp & 3;
        int l0   = k * CHUNK_L4;

        const float*  base = data + (size_t)b * C * L;
        const float4* b4   = (const float4*)base;

        int  l4  = l0 + (tid & 31);
        int  c0  = tid >> 5;                 // 0..7
        bool act = (l4 < zp4);

        float s = 0.0f, sq = 0.0f;
        if (act) {
            float4 v[8];
#pragma unroll
            for (int i = 0; i < 8; i++) {
                int c = c0 + i * 8;
                v[i] = b4[(size_t)c * L4 + l4];  // 8 independent loads in flight
            }
            float s0 = 0.f, q0 = 0.f, s1 = 0.f, q1 = 0.f;
#pragma unroll
            for (int i = 0; i < 8; i += 2) {
                s0 += v[i].x + v[i].y + v[i].z + v[i].w;
                q0 += v[i].x * v[i].x + v[i].y * v[i].y + v[i].z * v[i].z + v[i].w * v[i].w;
                s1 += v[i+1].x + v[i+1].y + v[i+1].z + v[i+1].w;
                q1 += v[i+1].x * v[i+1].x + v[i+1].y * v[i+1].y + v[i+1].z * v[i+1].z + v[i+1].w * v[i+1].w;
            }
            s  = s0 + s1;
            sq = q0 + q1;
        }

        // scalar remainder (zp % 4), all 64 rows, in the chunk containing zp4
        if (zp4 >= l0 && zp4 < l0 + CHUNK_L4 && (tid & 3) < zrem) {
            int c = tid >> 2;                 // 0..63
            float x = base[(size_t)c * L + (zp4 << 2) + (tid & 3)];
            s  += x;
            sq += x * x;
        }

        // block reduction for this unit
        sh_s[tid] = s;
        sh_q[tid] = sq;
        __syncthreads();
        for (int off = RED_THREADS / 2; off >= 32; off >>= 1) {
            if (tid < off) {
                sh_s[tid] += sh_s[tid + off];
                sh_q[tid] += sh_q[tid + off];
            }
            __syncthreads();
        }
        if (tid < 32) {
            float vs = sh_s[tid];
            float vq = sh_q[tid];
            for (int off = 16; off > 0; off >>= 1) {
                vs += __shfl_down_sync(0xFFFFFFFFu, vs, off);
                vq += __shfl_down_sync(0xFFFFFFFFu, vq, off);
            }
            if (tid == 0) {
                int slot = (b * MAX_C + k) * 2;
                g_partials[slot + 0] = vs;
                g_partials[slot + 1] = vq;
            }
        }
        __syncthreads();   // protect sh_s/sh_q reuse next unit
    }
}

// ---------------------------------------------------------------------------
// Kernel 2: fold partials -> scale = 1/(std+eps), bias = -mean*scale.
// Inactive chunk slots are never written and remain 0 (zero-init) -> correct.
// ---------------------------------------------------------------------------
__global__ void stats_kernel(const int* __restrict__ zero_pos, int C, int nslots) {
    int b = threadIdx.x;
    float s = 0.0f, sq = 0.0f;
    for (int j = 0; j < nslots; j++) {
        int slot = (b * MAX_C + j) * 2;
        s  += g_partials[slot + 0];
        sq += g_partials[slot + 1];
    }
    float cnt   = (float)C * (float)zero_pos[b];
    float mean  = s / cnt;
    float var   = (sq - cnt * mean * mean) / (cnt - 1.0f);
    float scale = 1.0f / (sqrtf(var) + EPS_F);
    g_stats[2 * b + 0] = scale;
    g_stats[2 * b + 1] = -mean * scale;
}

// ---------------------------------------------------------------------------
// Kernel 3: fused normalize + tail in ONE launch (R10 shape, unchanged).
// ---------------------------------------------------------------------------
__global__ void norm_tail_kernel(const float4* __restrict__ data4,
                                 const int4* __restrict__ idxes4,
                                 const int4* __restrict__ zp4,
                                 float4* __restrict__ out4,
                                 int nb_data, int cl4_shift,
                                 int n4, int nidx4, int ntail4) {
    if (blockIdx.x < nb_data) {
        int base = blockIdx.x * (256 * 4);
        int b    = base >> cl4_shift;           // uniform across block
        float scale = g_stats[2 * b + 0];
        float bias  = g_stats[2 * b + 1];

        int i0 = base + threadIdx.x;
        float4 v0 = data4[i0];
        float4 v1 = data4[i0 + 256];
        float4 v2 = data4[i0 + 512];
        float4 v3 = data4[i0 + 768];

        float4 o0, o1, o2, o3;
        o0.x = fmaf(v0.x, scale, bias); o0.y = fmaf(v0.y, scale, bias);
        o0.z = fmaf(v0.z, scale, bias); o0.w = fmaf(v0.w, scale, bias);
        o1.x = fmaf(v1.x, scale, bias); o1.y = fmaf(v1.y, scale, bias);
        o1.z = fmaf(v1.z, scale, bias); o1.w = fmaf(v1.w, scale, bias);
        o2.x = fmaf(v2.x, scale, bias); o2.y = fmaf(v2.y, scale, bias);
        o2.z = fmaf(v2.z, scale, bias); o2.w = fmaf(v2.w, scale, bias);
        o3.x = fmaf(v3.x, scale, bias); o3.y = fmaf(v3.y, scale, bias);
        o3.z = fmaf(v3.z, scale, bias); o3.w = fmaf(v3.w, scale, bias);

        __stcs(out4 + i0,       o0);
        __stcs(out4 + i0 + 256, o1);
        __stcs(out4 + i0 + 512, o2);
        __stcs(out4 + i0 + 768, o3);
    } else {
        int i = (blockIdx.x - nb_data) * 256 + threadIdx.x;
        if (i < ntail4) {
            int4 t = (i < nidx4) ? __ldcs(idxes4 + i) : __ldcs(zp4 + (i - nidx4));
            float4 o;
            o.x = (float)t.x; o.y = (float)t.y; o.z = (float)t.z; o.w = (float)t.w;
            __stcs(out4 + n4 + i, o);
        }
    }
}

extern "C" void kernel_launch(void* const* d_in, const int* in_sizes, int n_in,
                              void* d_out, int out_size) {
    const float* data     = (const float*)d_in[0];
    const int*   idxes    = (const int*)d_in[1];
    const int*   zero_pos = (const int*)d_in[2];
    float*       out      = (float*)d_out;

    int n_data = in_sizes[0];            // B*C*L = 33554432
    int n_idx  = in_sizes[1];            // B*L   = 524288
    int B      = in_sizes[2];            // 64
    int CL     = n_data / B;             // 524288
    int L      = n_idx / B;              // 8192
    int C      = CL / L;                 // 64

    // 1) balanced reduce over active 32KB chunks only
    reduce_kernel<<<RED_GRID, RED_THREADS>>>(data, zero_pos, C, L);

    // 2) stats
    int nchunks = (L / 4) / CHUNK_L4;    // 64 slots per batch
    stats_kernel<<<1, B>>>(zero_pos, C, nchunks);

    // 3) fused normalize + tail
    int n4  = n_data / 4;
    int cl4 = CL / 4;
    int cl4_shift = 0;
    while ((1 << cl4_shift) < cl4) cl4_shift++;   // CL/4 power of two

    int nb_data = n4 / (256 * 4);                 // exact tiling (8192 blocks)

    long long extra = (long long)out_size - (long long)n_data;
    int ntail4 = 0, nidx4 = n_idx / 4;
    if (extra > 0) {
        ntail4 = (int)(extra / 4);
        if (ntail4 > nidx4 + B / 4) ntail4 = nidx4 + B / 4;
    }
    int nb_tail = (ntail4 + 255) / 256;

    norm_tail_kernel<<<nb_data + nb_tail, 256>>>((const float4*)data,
                                                 (const int4*)idxes,
                                                 (const int4*)zero_pos,
                                                 (float4*)out,
                                                 nb_data, cl4_shift,
                                                 n4, nidx4, ntail4);
}

// round 13
// speedup vs baseline: 1.2550x; 1.2550x over previous
#include <cuda_runtime.h>
#include <math.h>

#define EPS_F 1.1920928955078125e-07f
#define RED_THREADS 256
#define MAX_C 64

// scratch (allocation-free rule): partial sums
__device__ float g_partials[256 * MAX_C * 2];  // [b][slot][{sum,sumsq}]

// ---------------------------------------------------------------------------
// Kernel 1: prefix sum & sumsq, TWO rows per block (R10 shape, 18.1us).
// grid = (B, C/2), 256 threads, 16 interleaved float4 loads/thread (MLP 16).
// ---------------------------------------------------------------------------
__global__ void reduce_kernel(const float* __restrict__ data,
                              const int* __restrict__ zero_pos,
                              int C, int L) {
    int b  = blockIdx.x;
    int c0 = blockIdx.y * 2;
    int zp = zero_pos[b];

    const float* row0 = data + ((size_t)b * C + c0) * L;
    const float* row1 = row0 + L;
    int zp4  = zp >> 2;
    int zrem = zp & 3;
    int tid  = threadIdx.x;

    const float4* r40 = (const float4*)row0;
    const float4* r41 = (const float4*)row1;

    float4 va[8], vb[8];
    int    valid[8];
#pragma unroll
    for (int k = 0; k < 8; k++) {
        int idx  = tid + k * RED_THREADS;
        valid[k] = (idx < zp4);
        if (valid[k]) { va[k] = r40[idx]; vb[k] = r41[idx]; }  // 16 loads in flight
    }

    float s0 = 0.f, q0 = 0.f, s1 = 0.f, q1 = 0.f;
#pragma unroll
    for (int k = 0; k < 8; k++) {
        if (valid[k]) {
            s0 += va[k].x + va[k].y + va[k].z + va[k].w;
            q0 += va[k].x * va[k].x + va[k].y * va[k].y + va[k].z * va[k].z + va[k].w * va[k].w;
            s1 += vb[k].x + vb[k].y + vb[k].z + vb[k].w;
            q1 += vb[k].x * vb[k].x + vb[k].y * vb[k].y + vb[k].z * vb[k].z + vb[k].w * vb[k].w;
        }
    }
    float s = s0 + s1, sq = q0 + q1;

    if (tid < zrem) {
        float x = row0[(zp4 << 2) + tid];
        float y = row1[(zp4 << 2) + tid];
        s  += x + y;
        sq += x * x + y * y;
    }

    // block reduction
    __shared__ float sh_s[RED_THREADS];
    __shared__ float sh_q[RED_THREADS];
    sh_s[tid] = s;
    sh_q[tid] = sq;
    __syncthreads();
    for (int off = RED_THREADS / 2; off >= 32; off >>= 1) {
        if (tid < off) {
            sh_s[tid] += sh_s[tid + off];
            sh_q[tid] += sh_q[tid + off];
        }
        __syncthreads();
    }
    if (tid < 32) {
        float vs = sh_s[tid];
        float vq = sh_q[tid];
        for (int off = 16; off > 0; off >>= 1) {
            vs += __shfl_down_sync(0xFFFFFFFFu, vs, off);
            vq += __shfl_down_sync(0xFFFFFFFFu, vq, off);
        }
        if (tid == 0) {
            int slot = (b * MAX_C + blockIdx.y) * 2;
            g_partials[slot + 0] = vs;
            g_partials[slot + 1] = vq;
        }
    }
}

// ---------------------------------------------------------------------------
// Kernel 2: fused normalize + tail; NO separate stats kernel.
// Each data block recomputes its own batch's stats from L2-hot partials
// (32 slot pairs summed by one warp, ~300cy, overlapped with the 4 global
// loads issued first). Kernel boundary orders partials writes before reads.
// ---------------------------------------------------------------------------
__global__ void norm_tail_kernel(const float4* __restrict__ data4,
                                 const int4* __restrict__ idxes4,
                                 const int4* __restrict__ zp4,
                                 const int* __restrict__ zero_pos,
                                 float4* __restrict__ out4,
                                 int nb_data, int cl4_shift,
                                 int n4, int nidx4, int ntail4,
                                 int nslots, int C) {
    if (blockIdx.x < nb_data) {
        int base = blockIdx.x * (256 * 4);
        int b    = base >> cl4_shift;           // uniform across block
        int tid  = threadIdx.x;

        // issue data loads first so they're in flight during stats compute
        int i0 = base + tid;
        float4 v0 = data4[i0];
        float4 v1 = data4[i0 + 256];
        float4 v2 = data4[i0 + 512];
        float4 v3 = data4[i0 + 768];

        // warp 0: fold this batch's partials (nslots = C/2 = 32 pairs)
        __shared__ float sh_scale, sh_bias;
        if (tid < 32) {
            float s  = 0.0f, sq = 0.0f;
            if (tid < nslots) {
                int slot = (b * MAX_C + tid) * 2;
                s  = g_partials[slot + 0];
                sq = g_partials[slot + 1];
            }
            for (int off = 16; off > 0; off >>= 1) {
                s  += __shfl_down_sync(0xFFFFFFFFu, s,  off);
                sq += __shfl_down_sync(0xFFFFFFFFu, sq, off);
            }
            if (tid == 0) {
                float cnt   = (float)C * (float)zero_pos[b];
                float mean  = s / cnt;
                float var   = (sq - cnt * mean * mean) / (cnt - 1.0f);
                float scale = 1.0f / (sqrtf(var) + EPS_F);
                sh_scale = scale;
                sh_bias  = -mean * scale;
            }
        }
        __syncthreads();
        float scale = sh_scale;
        float bias  = sh_bias;

        float4 o0, o1, o2, o3;
        o0.x = fmaf(v0.x, scale, bias); o0.y = fmaf(v0.y, scale, bias);
        o0.z = fmaf(v0.z, scale, bias); o0.w = fmaf(v0.w, scale, bias);
        o1.x = fmaf(v1.x, scale, bias); o1.y = fmaf(v1.y, scale, bias);
        o1.z = fmaf(v1.z, scale, bias); o1.w = fmaf(v1.w, scale, bias);
        o2.x = fmaf(v2.x, scale, bias); o2.y = fmaf(v2.y, scale, bias);
        o2.z = fmaf(v2.z, scale, bias); o2.w = fmaf(v2.w, scale, bias);
        o3.x = fmaf(v3.x, scale, bias); o3.y = fmaf(v3.y, scale, bias);
        o3.z = fmaf(v3.z, scale, bias); o3.w = fmaf(v3.w, scale, bias);

        __stcs(out4 + i0,       o0);
        __stcs(out4 + i0 + 256, o1);
        __stcs(out4 + i0 + 512, o2);
        __stcs(out4 + i0 + 768, o3);
    } else {
        int i = (blockIdx.x - nb_data) * 256 + threadIdx.x;
        if (i < ntail4) {
            int4 t = (i < nidx4) ? __ldcs(idxes4 + i) : __ldcs(zp4 + (i - nidx4));
            float4 o;
            o.x = (float)t.x; o.y = (float)t.y; o.z = (float)t.z; o.w = (float)t.w;
            __stcs(out4 + n4 + i, o);
        }
    }
}

extern "C" void kernel_launch(void* const* d_in, const int* in_sizes, int n_in,
                              void* d_out, int out_size) {
    const float* data     = (const float*)d_in[0];
    const int*   idxes    = (const int*)d_in[1];
    const int*   zero_pos = (const int*)d_in[2];
    float*       out      = (float*)d_out;

    int n_data = in_sizes[0];            // B*C*L = 33554432
    int n_idx  = in_sizes[1];            // B*L   = 524288
    int B      = in_sizes[2];            // 64
    int CL     = n_data / B;             // 524288
    int L      = n_idx / B;              // 8192
    int C      = CL / L;                 // 64

    // 1) reduce: two rows per block, MLP 16
    dim3 g1(B, C / 2);
    reduce_kernel<<<g1, RED_THREADS>>>(data, zero_pos, C, L);

    // 2) fused normalize + tail (stats folded into each norm block)
    int n4  = n_data / 4;
    int cl4 = CL / 4;
    int cl4_shift = 0;
    while ((1 << cl4_shift) < cl4) cl4_shift++;   // CL/4 power of two

    int nb_data = n4 / (256 * 4);                 // exact tiling (8192 blocks)

    long long extra = (long long)out_size - (long long)n_data;
    int ntail4 = 0, nidx4 = n_idx / 4;
    if (extra > 0) {
        ntail4 = (int)(extra / 4);
        if (ntail4 > nidx4 + B / 4) ntail4 = nidx4 + B / 4;
    }
    int nb_tail = (ntail4 + 255) / 256;

    norm_tail_kernel<<<nb_data + nb_tail, 256>>>((const float4*)data,
                                                 (const int4*)idxes,
                                                 (const int4*)zero_pos,
                                                 zero_pos,
                                                 (float4*)out,
                                                 nb_data, cl4_shift,
                                                 n4, nidx4, ntail4,
                                                 C / 2, C);
}